// round 10
// baseline (speedup 1.0000x reference)
#include <cuda_runtime.h>
#include <cuda_bf16.h>
#include <cstdint>

#define BB 2
#define NN 50
#define CC 80
#define MM 28
#define HH 800
#define WW 1333
#define HW (HH * WW)                          // 1,066,400 (div by 4)
#define HW4 (HW / 4)                          // 266,600 float4 groups
#define MASK_ELEMS ((long long)BB * NN * HW)  // 106,640,000
#define CHUNK 512                             // pixels per block (128 groups)
#define NCHUNK ((HW + CHUNK - 1) / CHUNK)     // 2083
#define TPB 128

// ---------------------------------------------------------------------------
// Single fused kernel (R7 per-thread shape; finer block granularity).
// Each block: one 512-pixel chunk of one batch, all 50 planes.
//  1. score-sorted instance table in shared + y-cull (order preserving:
//     first soft>=0.5 hit in sorted order IS the reference winner).
//  2. each thread computes winner bytes for its 4 pixels (bit-exact
//     reference float op sequence, no FMA contraction).
//  3. unconditional zero-blast: 50 aligned STG.128 streaming stores.
//  4. winner-plane float4 re-stores (same-thread order => ones after zeros).
// ---------------------------------------------------------------------------
__global__ __launch_bounds__(TPB) void det2mask_fused(
    const float* __restrict__ mask_outs,
    const float* __restrict__ boxes,
    const float* __restrict__ scores,
    const int*   __restrict__ cls,
    float* __restrict__ out,
    int writeTail)
{
    const int b      = blockIdx.y;
    const int t      = threadIdx.x;
    const int base_p = blockIdx.x * CHUNK;

    __shared__ float4 s_box[NN];
    __shared__ float4 s_bnd[NN];
    __shared__ int2   s_inf[NN];
    __shared__ unsigned char s_list[NN];
    __shared__ unsigned s_ballot[2];

    // --- 1a. sorted table -------------------------------------------------
    if (t < NN) {
        int i = b * NN + t;
        float s = scores[i];
        int rank = 0;
        #pragma unroll 1
        for (int j = 0; j < NN; j++) {
            float sj = scores[b * NN + j];
            rank += (sj > s) || (sj == s && j < t);
        }
        float x0 = boxes[i * 4 + 0], y0 = boxes[i * 4 + 1];
        float x1 = boxes[i * 4 + 2], y1 = boxes[i * 4 + 3];
        s_box[rank] = make_float4(x0, y0, x1, y1);
        float bw = x1 - x0, bh = y1 - y0;
        s_bnd[rank] = make_float4(x0 - 0.05f * bw - 1.0f,
                                  x1 + 0.05f * bw + 1.0f,
                                  y0 - 0.05f * bh - 1.0f,
                                  y1 + 0.05f * bh + 1.0f);
        s_inf[rank] = make_int2((i * CC + cls[i]) * (MM * MM), t);
    }
    if (writeTail && blockIdx.x == 0 && b == 0 && t < BB * NN) {
        out[MASK_ELEMS + t] = scores[t];
        out[MASK_ELEMS + BB * NN + t] = (float)cls[t];
    }
    __syncthreads();

    // --- 1b. y-range cull ---------------------------------------------------
    int pend = base_p + CHUNK; if (pend > HW) pend = HW;
    int y0r = base_p / WW;
    int y1r = (pend - 1) / WW;
    float tymin = (float)y0r + 0.5f, tymax = (float)y1r + 0.5f;

    if (t < 64) {
        bool hit = false;
        if (t < NN) {
            float4 bd = s_bnd[t];
            hit = (tymax >= bd.z) && (tymin <= bd.w);
        }
        unsigned m = __ballot_sync(0xffffffffu, hit);
        if ((t & 31) == 0) s_ballot[t >> 5] = m;
    }
    __syncthreads();
    if (t < 64) {
        unsigned m = s_ballot[t >> 5];
        if ((m >> (t & 31)) & 1u) {
            int pos = ((t >= 32) ? __popc(s_ballot[0]) : 0)
                      + __popc(m & ((1u << (t & 31)) - 1u));
            s_list[pos] = (unsigned char)t;
        }
    }
    __syncthreads();
    const int cnt = __popc(s_ballot[0]) + __popc(s_ballot[1]);

    // --- 2. winner bytes for this thread's 4 pixels -------------------------
    const int p0 = base_p + t * 4;
    const bool ok = (p0 < HW);
    unsigned wv = 0xffffffffu;                   // 255 = no winner
    if (ok && cnt > 0) {
        #pragma unroll
        for (int j = 0; j < 4; j++) {
            int p = p0 + j;
            int y = p / WW;
            int x = p - y * WW;
            float xc = (float)x + 0.5f;
            float yc = (float)y + 0.5f;
            int best = 255;
            #pragma unroll 1
            for (int kk = 0; kk < cnt; kk++) {
                int si = s_list[kk];
                float4 bd = s_bnd[si];
                if (xc < bd.x || xc > bd.y || yc < bd.z || yc > bd.w) continue;
                float4 bx = s_box[si];

                float ty_  = __fdiv_rn(__fsub_rn(yc, bx.y), __fsub_rn(bx.w, bx.y));
                float gy   = __fsub_rn(__fmul_rn(ty_, 2.0f), 1.0f);
                float iy   = __fmul_rn(__fsub_rn(__fmul_rn(__fadd_rn(gy, 1.0f), 28.0f), 1.0f), 0.5f);
                float iy0f = floorf(iy);
                float wy   = __fsub_rn(iy, iy0f);

                float tx_  = __fdiv_rn(__fsub_rn(xc, bx.x), __fsub_rn(bx.z, bx.x));
                float gx   = __fsub_rn(__fmul_rn(tx_, 2.0f), 1.0f);
                float ix   = __fmul_rn(__fsub_rn(__fmul_rn(__fadd_rn(gx, 1.0f), 28.0f), 1.0f), 0.5f);
                float ix0f = floorf(ix);
                float wx   = __fsub_rn(ix, ix0f);

                int iy0 = (int)iy0f;
                int ix0 = (int)ix0f;
                if (iy0 < -1 || iy0 > MM - 1 || ix0 < -1 || ix0 > MM - 1) continue;

                const float* mp = mask_outs + s_inf[si].x;
                int r0 = iy0, r1 = iy0 + 1;
                int c0 = ix0, c1 = ix0 + 1;
                float v00 = (r0 >= 0 && c0 >= 0)           ? mp[r0 * MM + c0] : 0.0f;
                float v01 = (r0 >= 0 && c1 <= MM - 1)      ? mp[r0 * MM + c1] : 0.0f;
                float v10 = (r1 <= MM - 1 && c0 >= 0)      ? mp[r1 * MM + c0] : 0.0f;
                float v11 = (r1 <= MM - 1 && c1 <= MM - 1) ? mp[r1 * MM + c1] : 0.0f;

                float omwy = __fsub_rn(1.0f, wy);
                float rr0  = __fadd_rn(__fmul_rn(v00, omwy), __fmul_rn(v10, wy));
                float rr1  = __fadd_rn(__fmul_rn(v01, omwy), __fmul_rn(v11, wy));
                float omwx = __fsub_rn(1.0f, wx);
                float soft = __fadd_rn(__fmul_rn(rr0, omwx), __fmul_rn(rr1, wx));

                if (soft >= 0.5f) { best = s_inf[si].y; break; }
            }
            wv = (wv & ~(0xffu << (j * 8))) | ((unsigned)best << (j * 8));
        }
    }

    // --- 3. zero-blast all 50 planes (aligned streaming stores) -------------
    if (ok) {
        float4* pl = reinterpret_cast<float4*>(out + b * (NN * HW)) + (p0 >> 2);
        const float4 z4 = make_float4(0.f, 0.f, 0.f, 0.f);
        #pragma unroll
        for (int n = 0; n < NN; n++) {
            __stcs(pl + n * HW4, z4);
        }

        // --- 4. winner-plane re-stores (<=4, same thread => ordered) --------
        if (wv != 0xffffffffu) {
            unsigned b0 =  wv        & 0xffu;
            unsigned b1 = (wv >> 8)  & 0xffu;
            unsigned b2 = (wv >> 16) & 0xffu;
            unsigned b3 =  wv >> 24;
            #pragma unroll
            for (int j = 0; j < 4; j++) {
                unsigned n = (wv >> (j * 8)) & 0xffu;
                if (n != 0xffu) {
                    float4 v;
                    v.x = (b0 == n) ? 1.0f : 0.0f;
                    v.y = (b1 == n) ? 1.0f : 0.0f;
                    v.z = (b2 == n) ? 1.0f : 0.0f;
                    v.w = (b3 == n) ? 1.0f : 0.0f;
                    __stcs(pl + (int)n * HW4, v);
                }
            }
        }
    }
}

extern "C" void kernel_launch(void* const* d_in, const int* in_sizes, int n_in,
                              void* d_out, int out_size)
{
    const float* mask_outs = (const float*)d_in[0];
    const float* boxes     = (const float*)d_in[1];
    const float* scores    = (const float*)d_in[2];
    const int*   cls       = (const int*)d_in[3];
    float* out = (float*)d_out;

    int writeTail = ((long long)out_size >= MASK_ELEMS + 2 * BB * NN) ? 1 : 0;
    dim3 grid(NCHUNK, BB);
    det2mask_fused<<<grid, TPB>>>(mask_outs, boxes, scores, cls, out, writeTail);
}

// round 11
// speedup vs baseline: 1.4665x; 1.4665x over previous
#include <cuda_runtime.h>
#include <cuda_bf16.h>
#include <cstdint>

#define BB 2
#define NN 50
#define CC 80
#define MM 28
#define HH 800
#define WW 1333
#define HW (HH * WW)                          // 1,066,400 (div by 4)
#define HW4 (HW / 4)                          // 266,600 float4 groups
#define MASK_ELEMS ((long long)BB * NN * HW)  // 106,640,000
#define CHUNK 1024                            // pixels per block (256 groups)
#define NCHUNK ((HW + CHUNK - 1) / CHUNK)     // 1042

// ---------------------------------------------------------------------------
// Single fused kernel (R7 structure — the measured optimum — plus rotated
// plane order in the zero-blast to decorrelate concurrent blocks across
// L2 partitions / DRAM banks).
// Each block: one 1024-pixel chunk of one batch, all 50 planes.
//  1. score-sorted instance table in shared + y-cull (order preserving:
//     first soft>=0.5 hit in sorted order IS the reference winner).
//  2. each thread computes winner bytes for its 4 pixels (bit-exact
//     reference float op sequence, no FMA contraction).
//  3. unconditional zero-blast: 50 aligned STG.128 streaming stores,
//     plane order rotated per block.
//  4. winner-plane float4 re-stores. All 50 zeros precede the re-stores in
//     this thread's program order => same-address ordering holds.
// ---------------------------------------------------------------------------
__global__ __launch_bounds__(256) void det2mask_fused(
    const float* __restrict__ mask_outs,
    const float* __restrict__ boxes,
    const float* __restrict__ scores,
    const int*   __restrict__ cls,
    float* __restrict__ out,
    int writeTail)
{
    const int b      = blockIdx.y;
    const int t      = threadIdx.x;
    const int base_p = blockIdx.x * CHUNK;

    __shared__ float4 s_box[NN];
    __shared__ float4 s_bnd[NN];
    __shared__ int2   s_inf[NN];
    __shared__ unsigned char s_list[NN];
    __shared__ unsigned s_ballot[2];

    // --- 1a. sorted table -------------------------------------------------
    if (t < NN) {
        int i = b * NN + t;
        float s = scores[i];
        int rank = 0;
        #pragma unroll 1
        for (int j = 0; j < NN; j++) {
            float sj = scores[b * NN + j];
            rank += (sj > s) || (sj == s && j < t);
        }
        float x0 = boxes[i * 4 + 0], y0 = boxes[i * 4 + 1];
        float x1 = boxes[i * 4 + 2], y1 = boxes[i * 4 + 3];
        s_box[rank] = make_float4(x0, y0, x1, y1);
        float bw = x1 - x0, bh = y1 - y0;
        s_bnd[rank] = make_float4(x0 - 0.05f * bw - 1.0f,
                                  x1 + 0.05f * bw + 1.0f,
                                  y0 - 0.05f * bh - 1.0f,
                                  y1 + 0.05f * bh + 1.0f);
        s_inf[rank] = make_int2((i * CC + cls[i]) * (MM * MM), t);
    }
    if (writeTail && blockIdx.x == 0 && b == 0 && t < BB * NN) {
        out[MASK_ELEMS + t] = scores[t];
        out[MASK_ELEMS + BB * NN + t] = (float)cls[t];
    }
    __syncthreads();

    // --- 1b. y-range cull ---------------------------------------------------
    int pend = base_p + CHUNK; if (pend > HW) pend = HW;
    int y0r = base_p / WW;
    int y1r = (pend - 1) / WW;
    float tymin = (float)y0r + 0.5f, tymax = (float)y1r + 0.5f;

    if (t < 64) {
        bool hit = false;
        if (t < NN) {
            float4 bd = s_bnd[t];
            hit = (tymax >= bd.z) && (tymin <= bd.w);
        }
        unsigned m = __ballot_sync(0xffffffffu, hit);
        if ((t & 31) == 0) s_ballot[t >> 5] = m;
    }
    __syncthreads();
    if (t < 64) {
        unsigned m = s_ballot[t >> 5];
        if ((m >> (t & 31)) & 1u) {
            int pos = ((t >= 32) ? __popc(s_ballot[0]) : 0)
                      + __popc(m & ((1u << (t & 31)) - 1u));
            s_list[pos] = (unsigned char)t;
        }
    }
    __syncthreads();
    const int cnt = __popc(s_ballot[0]) + __popc(s_ballot[1]);

    // --- 2. winner bytes for this thread's 4 pixels -------------------------
    const int p0 = base_p + t * 4;
    const bool ok = (p0 < HW);
    unsigned wv = 0xffffffffu;                   // 255 = no winner
    if (ok && cnt > 0) {
        #pragma unroll
        for (int j = 0; j < 4; j++) {
            int p = p0 + j;
            int y = p / WW;
            int x = p - y * WW;
            float xc = (float)x + 0.5f;
            float yc = (float)y + 0.5f;
            int best = 255;
            #pragma unroll 1
            for (int kk = 0; kk < cnt; kk++) {
                int si = s_list[kk];
                float4 bd = s_bnd[si];
                if (xc < bd.x || xc > bd.y || yc < bd.z || yc > bd.w) continue;
                float4 bx = s_box[si];

                float ty_  = __fdiv_rn(__fsub_rn(yc, bx.y), __fsub_rn(bx.w, bx.y));
                float gy   = __fsub_rn(__fmul_rn(ty_, 2.0f), 1.0f);
                float iy   = __fmul_rn(__fsub_rn(__fmul_rn(__fadd_rn(gy, 1.0f), 28.0f), 1.0f), 0.5f);
                float iy0f = floorf(iy);
                float wy   = __fsub_rn(iy, iy0f);

                float tx_  = __fdiv_rn(__fsub_rn(xc, bx.x), __fsub_rn(bx.z, bx.x));
                float gx   = __fsub_rn(__fmul_rn(tx_, 2.0f), 1.0f);
                float ix   = __fmul_rn(__fsub_rn(__fmul_rn(__fadd_rn(gx, 1.0f), 28.0f), 1.0f), 0.5f);
                float ix0f = floorf(ix);
                float wx   = __fsub_rn(ix, ix0f);

                int iy0 = (int)iy0f;
                int ix0 = (int)ix0f;
                if (iy0 < -1 || iy0 > MM - 1 || ix0 < -1 || ix0 > MM - 1) continue;

                const float* mp = mask_outs + s_inf[si].x;
                int r0 = iy0, r1 = iy0 + 1;
                int c0 = ix0, c1 = ix0 + 1;
                float v00 = (r0 >= 0 && c0 >= 0)           ? mp[r0 * MM + c0] : 0.0f;
                float v01 = (r0 >= 0 && c1 <= MM - 1)      ? mp[r0 * MM + c1] : 0.0f;
                float v10 = (r1 <= MM - 1 && c0 >= 0)      ? mp[r1 * MM + c0] : 0.0f;
                float v11 = (r1 <= MM - 1 && c1 <= MM - 1) ? mp[r1 * MM + c1] : 0.0f;

                float omwy = __fsub_rn(1.0f, wy);
                float rr0  = __fadd_rn(__fmul_rn(v00, omwy), __fmul_rn(v10, wy));
                float rr1  = __fadd_rn(__fmul_rn(v01, omwy), __fmul_rn(v11, wy));
                float omwx = __fsub_rn(1.0f, wx);
                float soft = __fadd_rn(__fmul_rn(rr0, omwx), __fmul_rn(rr1, wx));

                if (soft >= 0.5f) { best = s_inf[si].y; break; }
            }
            wv = (wv & ~(0xffu << (j * 8))) | ((unsigned)best << (j * 8));
        }
    }

    // --- 3. zero-blast all 50 planes, rotated start (streaming stores) -----
    if (ok) {
        float4* pl = reinterpret_cast<float4*>(out + b * (NN * HW)) + (p0 >> 2);
        const float4 z4 = make_float4(0.f, 0.f, 0.f, 0.f);
        const int rot = (blockIdx.x * 7) % NN;   // coprime stride rotation
        #pragma unroll
        for (int k = 0; k < NN; k++) {
            int n = rot + k; if (n >= NN) n -= NN;
            __stcs(pl + n * HW4, z4);
        }

        // --- 4. winner-plane re-stores (<=4, same thread => ordered) --------
        if (wv != 0xffffffffu) {
            unsigned b0 =  wv        & 0xffu;
            unsigned b1 = (wv >> 8)  & 0xffu;
            unsigned b2 = (wv >> 16) & 0xffu;
            unsigned b3 =  wv >> 24;
            #pragma unroll
            for (int j = 0; j < 4; j++) {
                unsigned n = (wv >> (j * 8)) & 0xffu;
                if (n != 0xffu) {
                    float4 v;
                    v.x = (b0 == n) ? 1.0f : 0.0f;
                    v.y = (b1 == n) ? 1.0f : 0.0f;
                    v.z = (b2 == n) ? 1.0f : 0.0f;
                    v.w = (b3 == n) ? 1.0f : 0.0f;
                    __stcs(pl + (int)n * HW4, v);
                }
            }
        }
    }
}

extern "C" void kernel_launch(void* const* d_in, const int* in_sizes, int n_in,
                              void* d_out, int out_size)
{
    const float* mask_outs = (const float*)d_in[0];
    const float* boxes     = (const float*)d_in[1];
    const float* scores    = (const float*)d_in[2];
    const int*   cls       = (const int*)d_in[3];
    float* out = (float*)d_out;

    int writeTail = ((long long)out_size >= MASK_ELEMS + 2 * BB * NN) ? 1 : 0;
    dim3 grid(NCHUNK, BB);
    det2mask_fused<<<grid, 256>>>(mask_outs, boxes, scores, cls, out, writeTail);
}

// round 12
// speedup vs baseline: 1.4828x; 1.0112x over previous
#include <cuda_runtime.h>
#include <cuda_bf16.h>
#include <cstdint>

#define BB 2
#define NN 50
#define CC 80
#define MM 28
#define HH 800
#define WW 1333
#define HW (HH * WW)                          // 1,066,400 (div by 4)
#define HW4 (HW / 4)                          // 266,600 float4 groups
#define MASK_ELEMS ((long long)BB * NN * HW)  // 106,640,000
#define CHUNK 1024                            // pixels per block (256 groups)
#define NCHUNK ((HW + CHUNK - 1) / CHUNK)     // 1042

// ---------------------------------------------------------------------------
// Single fused kernel (R7 geometry) with PER-WARP instance culling.
// Each block: one 1024-pixel chunk of one batch, all 50 planes.
//  1. score-sorted instance table in shared (stable desc sort, N=50).
//  2. per-warp cull: each warp spans 128 contiguous pixels (<=128 px in x,
//     <=2 rows). Ballot-compact (order-preserving!) the instances whose
//     conservative bounds overlap the warp window -> ~2-3 survivors vs ~14
//     for block-level y-culling. First soft>=0.5 hit in sorted order IS the
//     reference winner.
//  3. winner bytes for this thread's 4 pixels (bit-exact reference float
//     sequence, no FMA contraction).
//  4. zero-blast all 50 planes (aligned STG.128 streaming stores), then
//     winner-plane float4 re-stores (same-thread order => ones after zeros).
// ---------------------------------------------------------------------------
__global__ __launch_bounds__(256) void det2mask_fused(
    const float* __restrict__ mask_outs,
    const float* __restrict__ boxes,
    const float* __restrict__ scores,
    const int*   __restrict__ cls,
    float* __restrict__ out,
    int writeTail)
{
    const int b      = blockIdx.y;
    const int t      = threadIdx.x;
    const int base_p = blockIdx.x * CHUNK;

    __shared__ float4 s_box[NN];
    __shared__ float4 s_bnd[NN];
    __shared__ int2   s_inf[NN];
    __shared__ unsigned char s_wlist[8][56];   // per-warp culled list

    // --- 1. sorted table ---------------------------------------------------
    if (t < NN) {
        int i = b * NN + t;
        float s = scores[i];
        int rank = 0;
        #pragma unroll 1
        for (int j = 0; j < NN; j++) {
            float sj = scores[b * NN + j];
            rank += (sj > s) || (sj == s && j < t);
        }
        float x0 = boxes[i * 4 + 0], y0 = boxes[i * 4 + 1];
        float x1 = boxes[i * 4 + 2], y1 = boxes[i * 4 + 3];
        s_box[rank] = make_float4(x0, y0, x1, y1);
        float bw = x1 - x0, bh = y1 - y0;
        s_bnd[rank] = make_float4(x0 - 0.05f * bw - 1.0f,
                                  x1 + 0.05f * bw + 1.0f,
                                  y0 - 0.05f * bh - 1.0f,
                                  y1 + 0.05f * bh + 1.0f);
        s_inf[rank] = make_int2((i * CC + cls[i]) * (MM * MM), t);
    }
    if (writeTail && blockIdx.x == 0 && b == 0 && t < BB * NN) {
        out[MASK_ELEMS + t] = scores[t];
        out[MASK_ELEMS + BB * NN + t] = (float)cls[t];
    }
    __syncthreads();

    // --- 2. per-warp cull (order-preserving ballot compaction) --------------
    const int warp = t >> 5, lane = t & 31;
    const int wp0 = base_p + warp * 128;       // warp's first pixel
    int wc = 0;
    if (wp0 < HW) {
        int wpend = wp0 + 128; if (wpend > HW) wpend = HW;
        int yw0 = wp0 / WW;
        int yw1 = (wpend - 1) / WW;
        int xs  = wp0 - yw0 * WW;
        bool wrap = (yw1 != yw0);              // warp crosses a row boundary
        float wxmin = wrap ? 0.5f : (float)xs + 0.5f;
        float wxmax = wrap ? (float)WW - 0.5f : (float)xs + 127.5f;
        float wymin = (float)yw0 + 0.5f;
        float wymax = (float)yw1 + 0.5f;

        #pragma unroll
        for (int basei = 0; basei < NN; basei += 32) {
            int idx = basei + lane;
            bool h = false;
            if (idx < NN) {
                float4 bd = s_bnd[idx];
                h = (wxmax >= bd.x) && (wxmin <= bd.y) &&
                    (wymax >= bd.z) && (wymin <= bd.w);
            }
            unsigned m = __ballot_sync(0xffffffffu, h);
            if (h) {
                int pos = wc + __popc(m & ((1u << lane) - 1u));
                s_wlist[warp][pos] = (unsigned char)idx;
            }
            wc += __popc(m);
        }
        __syncwarp();
    }

    // --- 3. winner bytes for this thread's 4 pixels -------------------------
    const int p0 = base_p + t * 4;
    const bool ok = (p0 < HW);
    unsigned wv = 0xffffffffu;                   // 255 = no winner
    if (ok && wc > 0) {
        #pragma unroll
        for (int j = 0; j < 4; j++) {
            int p = p0 + j;
            int y = p / WW;
            int x = p - y * WW;
            float xc = (float)x + 0.5f;
            float yc = (float)y + 0.5f;
            int best = 255;
            #pragma unroll 1
            for (int kk = 0; kk < wc; kk++) {
                int si = s_wlist[warp][kk];
                float4 bd = s_bnd[si];
                if (xc < bd.x || xc > bd.y || yc < bd.z || yc > bd.w) continue;
                float4 bx = s_box[si];

                float ty_  = __fdiv_rn(__fsub_rn(yc, bx.y), __fsub_rn(bx.w, bx.y));
                float gy   = __fsub_rn(__fmul_rn(ty_, 2.0f), 1.0f);
                float iy   = __fmul_rn(__fsub_rn(__fmul_rn(__fadd_rn(gy, 1.0f), 28.0f), 1.0f), 0.5f);
                float iy0f = floorf(iy);
                float wy   = __fsub_rn(iy, iy0f);

                float tx_  = __fdiv_rn(__fsub_rn(xc, bx.x), __fsub_rn(bx.z, bx.x));
                float gx   = __fsub_rn(__fmul_rn(tx_, 2.0f), 1.0f);
                float ix   = __fmul_rn(__fsub_rn(__fmul_rn(__fadd_rn(gx, 1.0f), 28.0f), 1.0f), 0.5f);
                float ix0f = floorf(ix);
                float wx   = __fsub_rn(ix, ix0f);

                int iy0 = (int)iy0f;
                int ix0 = (int)ix0f;
                if (iy0 < -1 || iy0 > MM - 1 || ix0 < -1 || ix0 > MM - 1) continue;

                const float* mp = mask_outs + s_inf[si].x;
                int r0 = iy0, r1 = iy0 + 1;
                int c0 = ix0, c1 = ix0 + 1;
                float v00 = (r0 >= 0 && c0 >= 0)           ? mp[r0 * MM + c0] : 0.0f;
                float v01 = (r0 >= 0 && c1 <= MM - 1)      ? mp[r0 * MM + c1] : 0.0f;
                float v10 = (r1 <= MM - 1 && c0 >= 0)      ? mp[r1 * MM + c0] : 0.0f;
                float v11 = (r1 <= MM - 1 && c1 <= MM - 1) ? mp[r1 * MM + c1] : 0.0f;

                float omwy = __fsub_rn(1.0f, wy);
                float rr0  = __fadd_rn(__fmul_rn(v00, omwy), __fmul_rn(v10, wy));
                float rr1  = __fadd_rn(__fmul_rn(v01, omwy), __fmul_rn(v11, wy));
                float omwx = __fsub_rn(1.0f, wx);
                float soft = __fadd_rn(__fmul_rn(rr0, omwx), __fmul_rn(rr1, wx));

                if (soft >= 0.5f) { best = s_inf[si].y; break; }
            }
            wv = (wv & ~(0xffu << (j * 8))) | ((unsigned)best << (j * 8));
        }
    }

    // --- 4. zero-blast all 50 planes (aligned streaming stores) -------------
    if (ok) {
        float4* pl = reinterpret_cast<float4*>(out + b * (NN * HW)) + (p0 >> 2);
        const float4 z4 = make_float4(0.f, 0.f, 0.f, 0.f);
        #pragma unroll
        for (int n = 0; n < NN; n++) {
            __stcs(pl + n * HW4, z4);
        }

        // winner-plane re-stores (<=4, same thread => ordered)
        if (wv != 0xffffffffu) {
            unsigned b0 =  wv        & 0xffu;
            unsigned b1 = (wv >> 8)  & 0xffu;
            unsigned b2 = (wv >> 16) & 0xffu;
            unsigned b3 =  wv >> 24;
            #pragma unroll
            for (int j = 0; j < 4; j++) {
                unsigned n = (wv >> (j * 8)) & 0xffu;
                if (n != 0xffu) {
                    float4 v;
                    v.x = (b0 == n) ? 1.0f : 0.0f;
                    v.y = (b1 == n) ? 1.0f : 0.0f;
                    v.z = (b2 == n) ? 1.0f : 0.0f;
                    v.w = (b3 == n) ? 1.0f : 0.0f;
                    __stcs(pl + (int)n * HW4, v);
                }
            }
        }
    }
}

extern "C" void kernel_launch(void* const* d_in, const int* in_sizes, int n_in,
                              void* d_out, int out_size)
{
    const float* mask_outs = (const float*)d_in[0];
    const float* boxes     = (const float*)d_in[1];
    const float* scores    = (const float*)d_in[2];
    const int*   cls       = (const int*)d_in[3];
    float* out = (float*)d_out;

    int writeTail = ((long long)out_size >= MASK_ELEMS + 2 * BB * NN) ? 1 : 0;
    dim3 grid(NCHUNK, BB);
    det2mask_fused<<<grid, 256>>>(mask_outs, boxes, scores, cls, out, writeTail);
}